// round 16
// baseline (speedup 1.0000x reference)
#include <cuda_runtime.h>
#include <cuda_bf16.h>
#include <stdint.h>

// Problem constants (fixed by the dataset)
#define MAXN 50000
#define MAXE 500000
#define DIN  128

// packed fp32x2 FMA (sm_103a): d = a*b + d, elementwise on 2 packed fp32 lanes.
// ptxas never auto-generates FFMA2; PTX-only -> 2x fp32 FMA throughput.
#define FMA2(d, a, b) asm("fma.rn.f32x2 %0, %1, %2, %0;" : "+l"(d) : "l"(a), "l"(b))
#define DUP2(out, w)  asm("mov.b64 %0, {%1, %1};" : "=l"(out) : "r"(w))

// ---------------- scratch (device globals; no allocation allowed) ----------------
__device__ __align__(16) float g_Hs[(size_t)MAXN * 128];   // X@W1 (UNSCALED)
__device__ __align__(16) float g_h1[(size_t)MAXN * 128];   // relu(layer1 out)
__device__ __align__(16) float g_Gs[(size_t)MAXN * 64];    // (h1@W2)*dinv
__device__ int   g_cnt[MAXN];                // in-degree (no self loop)
__device__ int   g_fill[MAXN];               // fill cursors (init = rowptr by k_scanall)
__device__ int   g_rowptr[MAXN + 1];         // CSR row pointers (by dst)
__device__ int   g_srcs[MAXE];               // CSR column (src) indices
__device__ float g_dinv[MAXN];               // 1/sqrt(deg), deg = indeg+1

// ---------------- preprocessing ----------------
// edge_index is int32 (JAX x64 disabled)
__global__ void k_count(const int* __restrict__ ei, int E, int n) {
    int e = blockIdx.x * blockDim.x + threadIdx.x;
    if (e < E) {
        int d = ei[E + e];
        if ((unsigned)d < (unsigned)n)
            atomicAdd(&g_cnt[d], 1);
    }
}

// single-block exclusive scan of g_cnt (n <= 50176 = 1024*49).
// Two passes over per-thread contiguous segments + one 1024-wide block scan.
// Also emits dinv and pre-initializes g_fill = rowptr (absolute fill cursors).
__global__ void __launch_bounds__(1024, 1) k_scanall(int n) {
    __shared__ int sh[1024];
    const int t = threadIdx.x;
    const int PER = (n + 1023) / 1024;
    const int base = t * PER;
    const int lim = (base + PER < n) ? (base + PER) : n;

    // pass 1: segment sum
    int sum = 0;
    for (int i = base; i < lim; i++) sum += g_cnt[i];
    sh[t] = sum;
    __syncthreads();
    // inclusive Hillis-Steele over 1024 thread sums
    for (int off = 1; off < 1024; off <<= 1) {
        int v = 0;
        if (t >= off) v = sh[t - off];
        __syncthreads();
        sh[t] += v;
        __syncthreads();
    }
    int run = sh[t] - sum;                 // exclusive offset for this segment
    if (t == 1023) g_rowptr[n] = sh[1023]; // total valid edges

    // pass 2: per-element exclusive prefix + dinv + fill-cursor init
    for (int i = base; i < lim; i++) {
        int c = g_cnt[i];
        g_rowptr[i] = run;
        g_fill[i]   = run;
        g_dinv[i]   = rsqrtf((float)(c + 1));
        run += c;
    }
}

// g_fill holds absolute positions (pre-initialized to rowptr)
__global__ void k_fill(const int* __restrict__ ei, int E, int n) {
    int e = blockIdx.x * blockDim.x + threadIdx.x;
    if (e < E) {
        int s = ei[e];
        int d = ei[E + e];
        if ((unsigned)s < (unsigned)n && (unsigned)d < (unsigned)n) {
            int pos = atomicAdd(&g_fill[d], 1);
            g_srcs[pos] = s;
        }
    }
}

// ---------------- GEMM ----------------
// LAYER==1: out = Xin@W1, NO dinv scaling (runs concurrent with CSR build).
// LAYER==2: out = (g_h1@W2)*dinv.
// Node-pair-packed fma.rn.f32x2 accumulators: 32 FFMA2 per k per thread.
template <int F, int LAYER>
__global__ void __launch_bounds__(256, 2) k_gemm(const float* __restrict__ Xin,
                                                 const float* __restrict__ W, int n) {
    constexpr int CG  = F / 8;          // column groups (8 cols each)
    constexpr int NG  = 256 / CG;       // node groups
    constexpr int NPT = 8;              // nodes per thread (4 packed pairs)
    constexpr int NB  = NG * NPT;       // nodes per block (128 or 256)
    constexpr int KC  = 32;             // k-chunk
    constexpr int NBP = NB + 4;         // padded row stride

    __shared__ __align__(16) float sW[KC][F];
    __shared__ __align__(16) float sX[KC][NBP];

    const float* __restrict__ in;
    float* __restrict__ out;
    if (LAYER == 1) { in = Xin;   out = g_Hs; }
    else            { in = g_h1;  out = g_Gs; }

    const int tid = threadIdx.x;
    const int cg  = tid % CG;
    const int ng  = tid / CG;
    const int node0 = blockIdx.x * NB;

    unsigned long long acc[4][8];
    #pragma unroll
    for (int p = 0; p < 4; p++)
        #pragma unroll
        for (int c = 0; c < 8; c++) acc[p][c] = 0ull;

    for (int k0 = 0; k0 < DIN; k0 += KC) {
        {
            const float4* wsrc = (const float4*)(W + (size_t)k0 * F);
            float4* wdst = (float4*)&sW[0][0];
            #pragma unroll
            for (int i = tid; i < KC * F / 4; i += 256) wdst[i] = wsrc[i];
        }
        #pragma unroll
        for (int i = tid; i < NB * KC / 4; i += 256) {
            int r = i / (KC / 4);
            int c = i % (KC / 4);
            int node = node0 + r;
            float4 v = make_float4(0.f, 0.f, 0.f, 0.f);
            if (node < n) v = *(const float4*)(in + (size_t)node * DIN + k0 + c * 4);
            sX[c * 4 + 0][r] = v.x;
            sX[c * 4 + 1][r] = v.y;
            sX[c * 4 + 2][r] = v.z;
            sX[c * 4 + 3][r] = v.w;
        }
        __syncthreads();

        #pragma unroll
        for (int k = 0; k < KC; k++) {
            const float4 wa = *(const float4*)&sW[k][cg * 8];
            const float4 wb = *(const float4*)&sW[k][cg * 8 + 4];
            unsigned long long wd[8];
            DUP2(wd[0], __float_as_uint(wa.x)); DUP2(wd[1], __float_as_uint(wa.y));
            DUP2(wd[2], __float_as_uint(wa.z)); DUP2(wd[3], __float_as_uint(wa.w));
            DUP2(wd[4], __float_as_uint(wb.x)); DUP2(wd[5], __float_as_uint(wb.y));
            DUP2(wd[6], __float_as_uint(wb.z)); DUP2(wd[7], __float_as_uint(wb.w));
            const ulonglong2 xA = *(const ulonglong2*)&sX[k][ng * NPT];
            const ulonglong2 xB = *(const ulonglong2*)&sX[k][ng * NPT + 4];
            const unsigned long long xp[4] = { xA.x, xA.y, xB.x, xB.y };
            #pragma unroll
            for (int p = 0; p < 4; p++)
                #pragma unroll
                for (int c = 0; c < 8; c++)
                    FMA2(acc[p][c], xp[p], wd[c]);
        }
        __syncthreads();
    }

    #pragma unroll
    for (int p = 0; p < 4; p++) {
        float2 c0 = *(float2*)&acc[p][0], c1 = *(float2*)&acc[p][1];
        float2 c2 = *(float2*)&acc[p][2], c3 = *(float2*)&acc[p][3];
        float2 c4 = *(float2*)&acc[p][4], c5 = *(float2*)&acc[p][5];
        float2 c6 = *(float2*)&acc[p][6], c7 = *(float2*)&acc[p][7];
        int ne = node0 + ng * NPT + 2 * p;
        if (ne < n) {
            float dv = (LAYER == 2) ? g_dinv[ne] : 1.0f;
            float* o = out + (size_t)ne * F + cg * 8;
            *(float4*)(o)     = make_float4(c0.x * dv, c1.x * dv, c2.x * dv, c3.x * dv);
            *(float4*)(o + 4) = make_float4(c4.x * dv, c5.x * dv, c6.x * dv, c7.x * dv);
        }
        if (ne + 1 < n) {
            float dv = (LAYER == 2) ? g_dinv[ne + 1] : 1.0f;
            float* o = out + (size_t)(ne + 1) * F + cg * 8;
            *(float4*)(o)     = make_float4(c0.y * dv, c1.y * dv, c2.y * dv, c3.y * dv);
            *(float4*)(o + 4) = make_float4(c4.y * dv, c5.y * dv, c6.y * dv, c7.y * dv);
        }
    }
}

// ---------------- aggregation layer 1 ----------------
// Hs is UNSCALED: h1 = relu( dinv_i*( sum_e Hs[s]*dinv[s] + Hs[i]*dinv[i] ) + b1 )
// one warp per node; unroll-8 gather stage for deeper MLP (16 loads in flight).
__global__ void k_agg1(const float* __restrict__ bias, int n) {
    const int w = (blockIdx.x * blockDim.x + threadIdx.x) >> 5;
    const int lane = threadIdx.x & 31;
    if (w >= n) return;

    const int beg = g_rowptr[w];
    const int end = g_rowptr[w + 1];
    const float dv = g_dinv[w];

    const float4* __restrict__ H4 = (const float4*)g_Hs;
    float4 hs = H4[(size_t)w * 32 + lane];
    float4 a = make_float4(hs.x * dv, hs.y * dv, hs.z * dv, hs.w * dv); // self: Hs[i]*dinv[i]
    int e = beg;
    for (; e + 7 < end; e += 8) {
        int s0 = g_srcs[e],     s1 = g_srcs[e + 1], s2 = g_srcs[e + 2], s3 = g_srcs[e + 3];
        int s4 = g_srcs[e + 4], s5 = g_srcs[e + 5], s6 = g_srcs[e + 6], s7 = g_srcs[e + 7];
        float d0 = g_dinv[s0], d1 = g_dinv[s1], d2 = g_dinv[s2], d3 = g_dinv[s3];
        float d4 = g_dinv[s4], d5 = g_dinv[s5], d6 = g_dinv[s6], d7 = g_dinv[s7];
        float4 v0 = H4[(size_t)s0 * 32 + lane];
        float4 v1 = H4[(size_t)s1 * 32 + lane];
        float4 v2 = H4[(size_t)s2 * 32 + lane];
        float4 v3 = H4[(size_t)s3 * 32 + lane];
        float4 v4 = H4[(size_t)s4 * 32 + lane];
        float4 v5 = H4[(size_t)s5 * 32 + lane];
        float4 v6 = H4[(size_t)s6 * 32 + lane];
        float4 v7 = H4[(size_t)s7 * 32 + lane];
        a.x = fmaf(v0.x, d0, a.x); a.y = fmaf(v0.y, d0, a.y);
        a.z = fmaf(v0.z, d0, a.z); a.w = fmaf(v0.w, d0, a.w);
        a.x = fmaf(v1.x, d1, a.x); a.y = fmaf(v1.y, d1, a.y);
        a.z = fmaf(v1.z, d1, a.z); a.w = fmaf(v1.w, d1, a.w);
        a.x = fmaf(v2.x, d2, a.x); a.y = fmaf(v2.y, d2, a.y);
        a.z = fmaf(v2.z, d2, a.z); a.w = fmaf(v2.w, d2, a.w);
        a.x = fmaf(v3.x, d3, a.x); a.y = fmaf(v3.y, d3, a.y);
        a.z = fmaf(v3.z, d3, a.z); a.w = fmaf(v3.w, d3, a.w);
        a.x = fmaf(v4.x, d4, a.x); a.y = fmaf(v4.y, d4, a.y);
        a.z = fmaf(v4.z, d4, a.z); a.w = fmaf(v4.w, d4, a.w);
        a.x = fmaf(v5.x, d5, a.x); a.y = fmaf(v5.y, d5, a.y);
        a.z = fmaf(v5.z, d5, a.z); a.w = fmaf(v5.w, d5, a.w);
        a.x = fmaf(v6.x, d6, a.x); a.y = fmaf(v6.y, d6, a.y);
        a.z = fmaf(v6.z, d6, a.z); a.w = fmaf(v6.w, d6, a.w);
        a.x = fmaf(v7.x, d7, a.x); a.y = fmaf(v7.y, d7, a.y);
        a.z = fmaf(v7.z, d7, a.z); a.w = fmaf(v7.w, d7, a.w);
    }
    for (; e + 3 < end; e += 4) {
        int s0 = g_srcs[e], s1 = g_srcs[e + 1], s2 = g_srcs[e + 2], s3 = g_srcs[e + 3];
        float d0 = g_dinv[s0], d1 = g_dinv[s1], d2 = g_dinv[s2], d3 = g_dinv[s3];
        float4 v0 = H4[(size_t)s0 * 32 + lane];
        float4 v1 = H4[(size_t)s1 * 32 + lane];
        float4 v2 = H4[(size_t)s2 * 32 + lane];
        float4 v3 = H4[(size_t)s3 * 32 + lane];
        a.x = fmaf(v0.x, d0, a.x); a.y = fmaf(v0.y, d0, a.y);
        a.z = fmaf(v0.z, d0, a.z); a.w = fmaf(v0.w, d0, a.w);
        a.x = fmaf(v1.x, d1, a.x); a.y = fmaf(v1.y, d1, a.y);
        a.z = fmaf(v1.z, d1, a.z); a.w = fmaf(v1.w, d1, a.w);
        a.x = fmaf(v2.x, d2, a.x); a.y = fmaf(v2.y, d2, a.y);
        a.z = fmaf(v2.z, d2, a.z); a.w = fmaf(v2.w, d2, a.w);
        a.x = fmaf(v3.x, d3, a.x); a.y = fmaf(v3.y, d3, a.y);
        a.z = fmaf(v3.z, d3, a.z); a.w = fmaf(v3.w, d3, a.w);
    }
    for (; e < end; e++) {
        int s = g_srcs[e];
        float ds = g_dinv[s];
        float4 v = H4[(size_t)s * 32 + lane];
        a.x = fmaf(v.x, ds, a.x); a.y = fmaf(v.y, ds, a.y);
        a.z = fmaf(v.z, ds, a.z); a.w = fmaf(v.w, ds, a.w);
    }
    float4 bb = ((const float4*)bias)[lane];
    float4 o;
    o.x = fmaxf(a.x * dv + bb.x, 0.f);
    o.y = fmaxf(a.y * dv + bb.y, 0.f);
    o.z = fmaxf(a.z * dv + bb.z, 0.f);
    o.w = fmaxf(a.w * dv + bb.w, 0.f);
    ((float4*)g_h1)[(size_t)w * 32 + lane] = o;
}

// ---------------- aggregation layer 2: out = dinv*(gather + self) + b2 ----------------
// Gs is dinv-scaled already; half-warp per node: 16 lanes x float4 = 64-float row
__global__ void k_agg2(const float* __restrict__ bias, float* __restrict__ Yout, int n) {
    const int hw = (blockIdx.x * blockDim.x + threadIdx.x) >> 4;
    const int l  = threadIdx.x & 15;
    if (hw >= n) return;

    const int beg = g_rowptr[hw];
    const int end = g_rowptr[hw + 1];
    const float dv = g_dinv[hw];

    const float4* __restrict__ G4 = (const float4*)g_Gs;
    float4 a = G4[(size_t)hw * 16 + l];   // self-loop term
    int e = beg;
    for (; e + 3 < end; e += 4) {
        int s0 = g_srcs[e], s1 = g_srcs[e + 1], s2 = g_srcs[e + 2], s3 = g_srcs[e + 3];
        float4 v0 = G4[(size_t)s0 * 16 + l];
        float4 v1 = G4[(size_t)s1 * 16 + l];
        float4 v2 = G4[(size_t)s2 * 16 + l];
        float4 v3 = G4[(size_t)s3 * 16 + l];
        a.x += v0.x + v1.x + v2.x + v3.x;
        a.y += v0.y + v1.y + v2.y + v3.y;
        a.z += v0.z + v1.z + v2.z + v3.z;
        a.w += v0.w + v1.w + v2.w + v3.w;
    }
    for (; e < end; e++) {
        int s = g_srcs[e];
        float4 v = G4[(size_t)s * 16 + l];
        a.x += v.x; a.y += v.y; a.z += v.z; a.w += v.w;
    }
    float4 bb = ((const float4*)bias)[l];
    float4 o;
    o.x = a.x * dv + bb.x;
    o.y = a.y * dv + bb.y;
    o.z = a.z * dv + bb.z;
    o.w = a.w * dv + bb.w;
    ((float4*)Yout)[(size_t)hw * 16 + l] = o;
}

// ---------------- launch ----------------
extern "C" void kernel_launch(void* const* d_in, const int* in_sizes, int n_in,
                              void* d_out, int out_size) {
    const float* x  = (const float*)d_in[0];
    const int*   ei = (const int*)d_in[1];    // int32 (JAX x64 disabled)
    const float* W1 = (const float*)d_in[2];
    const float* b1 = (const float*)d_in[3];
    const float* W2 = (const float*)d_in[4];
    const float* b2 = (const float*)d_in[5];
    float*       out = (float*)d_out;

    const int n = in_sizes[0] / 128;   // 50000
    const int E = in_sizes[1] / 2;     // 500000

    // One-time host resources (no device allocation; identical work every call).
    static cudaStream_t s2 = nullptr;
    static cudaEvent_t evFork = nullptr, evJoin = nullptr;
    static void* p_cnt = nullptr;
    if (!s2) {
        cudaStreamCreateWithFlags(&s2, cudaStreamNonBlocking);
        cudaEventCreateWithFlags(&evFork, cudaEventDisableTiming);
        cudaEventCreateWithFlags(&evJoin, cudaEventDisableTiming);
        cudaGetSymbolAddress(&p_cnt, g_cnt);
    }

    // ---- fork: gemm1 (needs only x, W1) runs concurrent with the CSR build ----
    cudaEventRecord(evFork, 0);
    cudaStreamWaitEvent(s2, evFork, 0);
    k_gemm<128, 1><<<(n + 127) / 128, 256, 0, s2>>>(x, W1, n);
    cudaEventRecord(evJoin, s2);

    // ---- CSR build chain (stream 0) ----
    cudaMemsetAsync(p_cnt, 0, (size_t)n * sizeof(int), 0);
    k_count<<<(E + 255) / 256, 256>>>(ei, E, n);
    k_scanall<<<1, 1024>>>(n);
    k_fill<<<(E + 255) / 256, 256>>>(ei, E, n);

    // ---- join, then layer-1 aggregation ----
    cudaStreamWaitEvent(0, evJoin, 0);
    k_agg1<<<(n + 15) / 16, 512>>>(b1, n);

    // ---- layer 2 (serial chain) ----
    k_gemm<64, 2><<<(n + 255) / 256, 256>>>(nullptr, W2, n);
    k_agg2<<<(n + 15) / 16, 256>>>(b2, out, n);
}